// round 1
// baseline (speedup 1.0000x reference)
#include <cuda_runtime.h>
#include <stdint.h>

constexpr int B_N = 8;
constexpr int A_N = 100000;
constexpr int C_N = 80;
constexpr int M_N = 50;
constexpr int H_N = 512, W_N = 512;
constexpr int NB  = (A_N + 255) / 256;   // 391 blocks per sample

// 0 = bool/uint8, 1 = float32, 2 = int32
__device__ int   g_kind;
__device__ float g_partials[B_N * NB * 4];

// ---------------------------------------------------------------------------
// Kernel 0: classify the dtype of `states` by bit pattern (deterministic).
// Buffer is at least B*H*W = 2,097,152 bytes under any interpretation, so
// scanning 262144 uint32 words (1 MB) is always in-bounds.
// ---------------------------------------------------------------------------
__global__ void k_detect(const uint32_t* __restrict__ s) {
    bool fl = true, il = true;
    for (int i = threadIdx.x; i < 262144; i += 256) {
        uint32_t v = s[i];
        fl = fl && (v == 0u || v == 0x3F800000u);
        il = il && (v <= 1u);
    }
    __shared__ int sf, si;
    if (threadIdx.x == 0) { sf = 1; si = 1; }
    __syncthreads();
    if (!fl) atomicAnd(&sf, 0);
    if (!il) atomicAnd(&si, 0);
    __syncthreads();
    if (threadIdx.x == 0) g_kind = sf ? 1 : (si ? 2 : 0);
}

// target==0 focal term (without the (1-ALPHA) factor, folded into the weight)
__device__ __forceinline__ float focneg(float c) {
    c = fminf(fmaxf(c, 1e-4f), 0.9999f);
    return c * c * (-__logf(1.0f - c));
}

// ---------------------------------------------------------------------------
// Kernel 1: main pass. grid = (NB, B), block = 256.
// Phase 1: per-thread anchor assignment (argmin over 50 annotations in smem),
//          pos/neg gates, damp lookup, pos-anchor corrections + regression.
// Phase 2: warp-cooperative, fully coalesced float4 stream of the 32-anchor
//          classification block (10240 B contiguous per warp).
// Phase 3: deterministic block tree-reduction -> per-block partials.
// ---------------------------------------------------------------------------
__global__ void __launch_bounds__(256) k_main(
    const float* __restrict__ cls,     // (B, A, C)
    const float* __restrict__ reg,     // (B, A, 3)
    const float* __restrict__ anc,     // (1, A, 3)
    const float* __restrict__ ann,     // (B, M, 4)
    const void*  __restrict__ states)  // (B, 1, H, W)
{
    const int b    = blockIdx.y;
    const int blk  = blockIdx.x;
    const int tid  = threadIdx.x;
    const int warp = tid >> 5, lane = tid & 31;

    __shared__ float  s_ax[M_N], s_ay[M_N], s_aa[M_N], s_ac[M_N];
    __shared__ float  s_w[8][32];
    __shared__ float4 s_red[256];

    if (tid < M_N) {
        const float* p = ann + (b * M_N + tid) * 4;
        s_ax[tid] = p[0]; s_ay[tid] = p[1]; s_aa[tid] = p[2]; s_ac[tid] = p[3];
    }
    __syncthreads();

    const int a = blk * 256 + tid;
    float acc_c = 0.f, acc_n = 0.f, acc_xy = 0.f, acc_an = 0.f;
    float wv = 0.f;

    if (a < A_N) {
        float ax = anc[a * 3 + 0], ay = anc[a * 3 + 1], aal = anc[a * 3 + 2];

        // nearest annotation by squared xy distance (first-index tie-break)
        float best = 3.4e38f; int bm = 0;
        #pragma unroll 10
        for (int m = 0; m < M_N; m++) {
            float dx = ax - s_ax[m];
            float dy = ay - s_ay[m];
            float d2 = fmaf(dx, dx, dy * dy);
            if (d2 < best) { best = d2; bm = m; }
        }
        float asx = s_ax[bm], asy = s_ay[bm], asa = s_aa[bm], asc = s_ac[bm];
        float dal = fabsf(aal - asa);

        bool pos = (best <= 25.0f)   && (dal <= 10.0f);   // dxy<=5, dal<=10
        bool neg = (best >= 56.25f)  || (dal >= 15.0f);   // dxy>=7.5 or dal>=15

        // gt map lookup: state[b,0,round(ay),round(ax)], half-to-even rounding
        int ix = __float2int_rn(ax);
        int iy = __float2int_rn(ay);
        long sidx = (long)b * (H_N * W_N) + (long)iy * W_N + ix;
        int kind = g_kind;
        bool gt;
        if (kind == 1)      gt = ((const float*)states)[sidx] != 0.0f;
        else if (kind == 2) gt = ((const int*)states)[sidx]   != 0;
        else                gt = ((const unsigned char*)states)[sidx] != 0;
        float damp = gt ? 1.0f : 0.1f;

        // weight for the generic target-0 focal term, (1-ALPHA)=0.05 folded in
        wv = (pos || neg) ? damp * 0.05f : 0.0f;

        if (pos) {
            acc_n = 1.0f;
            // classification correction at the assigned class
            int k = (int)asc;
            float ck = cls[((size_t)b * A_N + a) * C_N + k];
            ck = fminf(fmaxf(ck, 1e-4f), 0.9999f);
            float omc = 1.0f - ck;
            float corr = damp * (0.95f * omc * omc * (-__logf(ck))
                               - 0.05f * ck  * ck  * (-__logf(omc)));
            acc_c += corr;

            // regression losses (only pos anchors contribute)
            const float* r = reg + ((size_t)b * A_N + a) * 3;
            float d0 = fabsf((asx - ax)  - r[0]);
            float d1 = fabsf((asy - ay)  - r[1]);
            float da = fmaxf((fabsf((asa - aal) - r[2]) - 10.0f) * 0.2f, 0.0f);
            float l0 = (d0 <= (1.0f / 9.0f)) ? 4.5f * d0 * d0 : d0 - (1.0f / 18.0f);
            float l1 = (d1 <= (1.0f / 9.0f)) ? 4.5f * d1 * d1 : d1 - (1.0f / 18.0f);
            acc_xy = damp * (l0 + l1);
            acc_an = damp * da;
        }
    }
    s_w[warp][lane] = wv;
    __syncwarp();

    // Phase 2: coalesced stream of this warp's 32 anchors x 80 classes.
    // A_N % 32 == 0, so warps are either fully valid or fully out of range.
    const int wbase = blk * 256 + warp * 32;
    if (wbase < A_N) {
        const float4* p4 = (const float4*)(cls + ((size_t)b * A_N + wbase) * C_N);
        #pragma unroll 4
        for (int j = 0; j < 20; j++) {
            int i4 = j * 32 + lane;               // float4 index within warp block
            float4 v = __ldcs(p4 + i4);           // streaming, evict-first
            float  w = s_w[warp][i4 / 20];        // 20 float4 per anchor
            float  t = focneg(v.x) + focneg(v.y) + focneg(v.z) + focneg(v.w);
            acc_c = fmaf(w, t, acc_c);
        }
    }

    // Phase 3: deterministic block reduction of (cls, npos, xy, ang)
    __syncthreads();
    s_red[tid] = make_float4(acc_c, acc_n, acc_xy, acc_an);
    __syncthreads();
    for (int s = 128; s > 0; s >>= 1) {
        if (tid < s) {
            float4 o = s_red[tid + s];
            float4 m = s_red[tid];
            m.x += o.x; m.y += o.y; m.z += o.z; m.w += o.w;
            s_red[tid] = m;
        }
        __syncthreads();
    }
    if (tid == 0) {
        float4 t = s_red[0];
        float* p = &g_partials[((size_t)b * NB + blk) * 4];
        p[0] = t.x; p[1] = t.y; p[2] = t.z; p[3] = t.w;
    }
}

// ---------------------------------------------------------------------------
// Kernel 2: deterministic final reduction over blocks and samples.
// ---------------------------------------------------------------------------
__global__ void k_reduce(float* __restrict__ out) {
    __shared__ float4 s_red[256];
    const int tid = threadIdx.x;
    float cl = 0.f, xl = 0.f, al = 0.f;

    for (int smp = 0; smp < B_N; smp++) {
        float4 acc = make_float4(0.f, 0.f, 0.f, 0.f);
        for (int i = tid; i < NB; i += 256) {
            const float* p = &g_partials[((size_t)smp * NB + i) * 4];
            acc.x += p[0]; acc.y += p[1]; acc.z += p[2]; acc.w += p[3];
        }
        s_red[tid] = acc;
        __syncthreads();
        for (int s = 128; s > 0; s >>= 1) {
            if (tid < s) {
                float4 o = s_red[tid + s];
                float4 m = s_red[tid];
                m.x += o.x; m.y += o.y; m.z += o.z; m.w += o.w;
                s_red[tid] = m;
            }
            __syncthreads();
        }
        if (tid == 0) {
            float4 t  = s_red[0];
            float  np = fmaxf(t.y, 1.0f);
            cl += t.x / np;
            if (t.y > 0.0f) {
                xl += t.z / (2.0f * np);
                al += t.w / np;
            }
        }
        __syncthreads();
    }
    if (tid == 0) {
        out[0] = cl * 0.125f;
        out[1] = xl * 0.125f;
        out[2] = al * 0.125f;
    }
}

// ---------------------------------------------------------------------------
extern "C" void kernel_launch(void* const* d_in, const int* in_sizes, int n_in,
                              void* d_out, int out_size) {
    (void)in_sizes; (void)n_in; (void)out_size;
    const float* cls     = (const float*)d_in[0];
    const float* reg     = (const float*)d_in[1];
    const float* anchors = (const float*)d_in[2];
    const float* ann     = (const float*)d_in[3];
    const void*  states  = d_in[4];

    k_detect<<<1, 256>>>((const uint32_t*)states);
    dim3 grid(NB, B_N);
    k_main<<<grid, 256>>>(cls, reg, anchors, ann, states);
    k_reduce<<<1, 256>>>((float*)d_out);
}

// round 2
// speedup vs baseline: 1.2874x; 1.2874x over previous
#include <cuda_runtime.h>
#include <stdint.h>

constexpr int B_N = 8;
constexpr int A_N = 100000;
constexpr int C_N = 80;
constexpr int M_N = 50;
constexpr int H_N = 512, W_N = 512;
constexpr int NB  = (A_N + 255) / 256;   // 391 blocks per sample

// dtype flags for `states`: g_fl = "all words are 0.0f or 1.0f bit patterns",
// g_il = "all words <= 1".  kind: fl -> float32, else il -> int32, else bool8.
__device__ int   g_fl, g_il;
__device__ float g_partials[B_N * NB * 4];

// ---------------------------------------------------------------------------
// Kernel -1: initialize detection flags (graph-capturable, deterministic).
// ---------------------------------------------------------------------------
__global__ void k_init() { g_fl = 1; g_il = 1; }

// ---------------------------------------------------------------------------
// Kernel 0: parallel dtype classification of `states` by bit pattern.
// Buffer is at least B*H*W = 2,097,152 bytes under any interpretation, so
// scanning 262144 uint32 words (1 MB) is always in-bounds.
// grid = 256 blocks x 256 threads -> 4 words per thread.
// ---------------------------------------------------------------------------
__global__ void __launch_bounds__(256) k_detect(const uint32_t* __restrict__ s) {
    const int stride = 256 * 256;
    bool fl = true, il = true;
    for (int i = blockIdx.x * 256 + threadIdx.x; i < 262144; i += stride) {
        uint32_t v = __ldcs(s + i);
        fl = fl && (v == 0u || v == 0x3F800000u);
        il = il && (v <= 1u);
    }
    // warp reduce
    unsigned bf = __ballot_sync(0xFFFFFFFFu, fl);
    unsigned bi = __ballot_sync(0xFFFFFFFFu, il);
    __shared__ int sf, si;
    if (threadIdx.x == 0) { sf = 1; si = 1; }
    __syncthreads();
    if ((threadIdx.x & 31) == 0) {
        if (bf != 0xFFFFFFFFu) atomicAnd(&sf, 0);
        if (bi != 0xFFFFFFFFu) atomicAnd(&si, 0);
    }
    __syncthreads();
    if (threadIdx.x == 0) {
        if (!sf) atomicAnd(&g_fl, 0);
        if (!si) atomicAnd(&g_il, 0);
    }
}

// target==0 focal term (without the (1-ALPHA) factor, folded into the weight)
__device__ __forceinline__ float focneg(float c) {
    c = fminf(fmaxf(c, 1e-4f), 0.9999f);
    return c * c * (-__logf(1.0f - c));
}

// ---------------------------------------------------------------------------
// Kernel 1: main pass. grid = (NB, B), block = 256.
// Phase 1: per-thread anchor assignment (argmin over 50 annotations in smem),
//          pos/neg gates, damp lookup, pos-anchor corrections + regression.
// Phase 2: warp-cooperative, fully coalesced float4 stream of the 32-anchor
//          classification block (10240 B contiguous per warp).
// Phase 3: deterministic block tree-reduction -> per-block partials.
// ---------------------------------------------------------------------------
__global__ void __launch_bounds__(256) k_main(
    const float* __restrict__ cls,     // (B, A, C)
    const float* __restrict__ reg,     // (B, A, 3)
    const float* __restrict__ anc,     // (1, A, 3)
    const float* __restrict__ ann,     // (B, M, 4)
    const void*  __restrict__ states)  // (B, 1, H, W)
{
    const int b    = blockIdx.y;
    const int blk  = blockIdx.x;
    const int tid  = threadIdx.x;
    const int warp = tid >> 5, lane = tid & 31;

    __shared__ float  s_ax[M_N], s_ay[M_N], s_aa[M_N], s_ac[M_N];
    __shared__ float  s_w[8][32];
    __shared__ float4 s_red[256];

    if (tid < M_N) {
        const float* p = ann + (b * M_N + tid) * 4;
        s_ax[tid] = p[0]; s_ay[tid] = p[1]; s_aa[tid] = p[2]; s_ac[tid] = p[3];
    }
    __syncthreads();

    const int a = blk * 256 + tid;
    float acc_c = 0.f, acc_n = 0.f, acc_xy = 0.f, acc_an = 0.f;
    float wv = 0.f;

    if (a < A_N) {
        float ax = anc[a * 3 + 0], ay = anc[a * 3 + 1], aal = anc[a * 3 + 2];

        // nearest annotation by squared xy distance (first-index tie-break)
        float best = 3.4e38f; int bm = 0;
        #pragma unroll 10
        for (int m = 0; m < M_N; m++) {
            float dx = ax - s_ax[m];
            float dy = ay - s_ay[m];
            float d2 = fmaf(dx, dx, dy * dy);
            if (d2 < best) { best = d2; bm = m; }
        }
        float asx = s_ax[bm], asy = s_ay[bm], asa = s_aa[bm], asc = s_ac[bm];
        float dal = fabsf(aal - asa);

        bool pos = (best <= 25.0f)   && (dal <= 10.0f);   // dxy<=5, dal<=10
        bool neg = (best >= 56.25f)  || (dal >= 15.0f);   // dxy>=7.5 or dal>=15

        // gt map lookup: state[b,0,round(ay),round(ax)], half-to-even rounding
        int ix = __float2int_rn(ax);
        int iy = __float2int_rn(ay);
        long sidx = (long)b * (H_N * W_N) + (long)iy * W_N + ix;
        int kind = g_fl ? 1 : (g_il ? 2 : 0);
        bool gt;
        if (kind == 1)      gt = ((const float*)states)[sidx] != 0.0f;
        else if (kind == 2) gt = ((const int*)states)[sidx]   != 0;
        else                gt = ((const unsigned char*)states)[sidx] != 0;
        float damp = gt ? 1.0f : 0.1f;

        // weight for the generic target-0 focal term, (1-ALPHA)=0.05 folded in
        wv = (pos || neg) ? damp * 0.05f : 0.0f;

        if (pos) {
            acc_n = 1.0f;
            // classification correction at the assigned class
            int k = (int)asc;
            float ck = cls[((size_t)b * A_N + a) * C_N + k];
            ck = fminf(fmaxf(ck, 1e-4f), 0.9999f);
            float omc = 1.0f - ck;
            float corr = damp * (0.95f * omc * omc * (-__logf(ck))
                               - 0.05f * ck  * ck  * (-__logf(omc)));
            acc_c += corr;

            // regression losses (only pos anchors contribute)
            const float* r = reg + ((size_t)b * A_N + a) * 3;
            float d0 = fabsf((asx - ax)  - r[0]);
            float d1 = fabsf((asy - ay)  - r[1]);
            float da = fmaxf((fabsf((asa - aal) - r[2]) - 10.0f) * 0.2f, 0.0f);
            float l0 = (d0 <= (1.0f / 9.0f)) ? 4.5f * d0 * d0 : d0 - (1.0f / 18.0f);
            float l1 = (d1 <= (1.0f / 9.0f)) ? 4.5f * d1 * d1 : d1 - (1.0f / 18.0f);
            acc_xy = damp * (l0 + l1);
            acc_an = damp * da;
        }
    }
    s_w[warp][lane] = wv;
    __syncwarp();

    // Phase 2: coalesced stream of this warp's 32 anchors x 80 classes.
    // A_N % 32 == 0, so warps are either fully valid or fully out of range.
    const int wbase = blk * 256 + warp * 32;
    if (wbase < A_N) {
        const float4* p4 = (const float4*)(cls + ((size_t)b * A_N + wbase) * C_N);
        #pragma unroll 4
        for (int j = 0; j < 20; j++) {
            int i4 = j * 32 + lane;               // float4 index within warp block
            float4 v = __ldcs(p4 + i4);           // streaming, evict-first
            float  w = s_w[warp][i4 / 20];        // 20 float4 per anchor
            float  t = focneg(v.x) + focneg(v.y) + focneg(v.z) + focneg(v.w);
            acc_c = fmaf(w, t, acc_c);
        }
    }

    // Phase 3: deterministic block reduction of (cls, npos, xy, ang)
    __syncthreads();
    s_red[tid] = make_float4(acc_c, acc_n, acc_xy, acc_an);
    __syncthreads();
    for (int s = 128; s > 0; s >>= 1) {
        if (tid < s) {
            float4 o = s_red[tid + s];
            float4 m = s_red[tid];
            m.x += o.x; m.y += o.y; m.z += o.z; m.w += o.w;
            s_red[tid] = m;
        }
        __syncthreads();
    }
    if (tid == 0) {
        float4 t = s_red[0];
        float* p = &g_partials[((size_t)b * NB + blk) * 4];
        p[0] = t.x; p[1] = t.y; p[2] = t.z; p[3] = t.w;
    }
}

// ---------------------------------------------------------------------------
// Kernel 2: deterministic final reduction over blocks and samples.
// ---------------------------------------------------------------------------
__global__ void k_reduce(float* __restrict__ out) {
    __shared__ float4 s_red[256];
    const int tid = threadIdx.x;
    float cl = 0.f, xl = 0.f, al = 0.f;

    for (int smp = 0; smp < B_N; smp++) {
        float4 acc = make_float4(0.f, 0.f, 0.f, 0.f);
        for (int i = tid; i < NB; i += 256) {
            const float* p = &g_partials[((size_t)smp * NB + i) * 4];
            acc.x += p[0]; acc.y += p[1]; acc.z += p[2]; acc.w += p[3];
        }
        s_red[tid] = acc;
        __syncthreads();
        for (int s = 128; s > 0; s >>= 1) {
            if (tid < s) {
                float4 o = s_red[tid + s];
                float4 m = s_red[tid];
                m.x += o.x; m.y += o.y; m.z += o.z; m.w += o.w;
                s_red[tid] = m;
            }
            __syncthreads();
        }
        if (tid == 0) {
            float4 t  = s_red[0];
            float  np = fmaxf(t.y, 1.0f);
            cl += t.x / np;
            if (t.y > 0.0f) {
                xl += t.z / (2.0f * np);
                al += t.w / np;
            }
        }
        __syncthreads();
    }
    if (tid == 0) {
        out[0] = cl * 0.125f;
        out[1] = xl * 0.125f;
        out[2] = al * 0.125f;
    }
}

// ---------------------------------------------------------------------------
extern "C" void kernel_launch(void* const* d_in, const int* in_sizes, int n_in,
                              void* d_out, int out_size) {
    (void)in_sizes; (void)n_in; (void)out_size;
    const float* cls     = (const float*)d_in[0];
    const float* reg     = (const float*)d_in[1];
    const float* anchors = (const float*)d_in[2];
    const float* ann     = (const float*)d_in[3];
    const void*  states  = d_in[4];

    k_init<<<1, 1>>>();
    k_detect<<<256, 256>>>((const uint32_t*)states);
    dim3 grid(NB, B_N);
    k_main<<<grid, 256>>>(cls, reg, anchors, ann, states);
    k_reduce<<<1, 256>>>((float*)d_out);
}

// round 3
// speedup vs baseline: 1.4831x; 1.1520x over previous
#include <cuda_runtime.h>
#include <stdint.h>

constexpr int B_N = 8;
constexpr int A_N = 100000;
constexpr int C_N = 80;
constexpr int M_N = 50;
constexpr int H_N = 512, W_N = 512;
constexpr int NB  = (A_N + 255) / 256;   // 391 blocks per sample

// dtype flags for `states`: g_fl = "all words are 0.0f or 1.0f bit patterns",
// g_il = "all words <= 1".  kind: fl -> float32, else il -> int32, else bool8.
__device__ int   g_fl, g_il;
__device__ int   g_done;
__device__ float g_partials[B_N * NB * 4];
__device__ float g_samples[B_N * 3];

// ---------------------------------------------------------------------------
// Kernel -1: initialize flags + completion counter (graph-capturable).
// ---------------------------------------------------------------------------
__global__ void k_init() { g_fl = 1; g_il = 1; g_done = 0; }

// ---------------------------------------------------------------------------
// Kernel 0: parallel dtype classification of `states` by bit pattern.
// Buffer is at least B*H*W = 2,097,152 bytes under any interpretation, so
// scanning 262144 uint32 words (1 MB) is always in-bounds.
// ---------------------------------------------------------------------------
__global__ void __launch_bounds__(256) k_detect(const uint32_t* __restrict__ s) {
    const int stride = 256 * 256;
    bool fl = true, il = true;
    for (int i = blockIdx.x * 256 + threadIdx.x; i < 262144; i += stride) {
        uint32_t v = __ldcs(s + i);
        fl = fl && (v == 0u || v == 0x3F800000u);
        il = il && (v <= 1u);
    }
    unsigned bf = __ballot_sync(0xFFFFFFFFu, fl);
    unsigned bi = __ballot_sync(0xFFFFFFFFu, il);
    __shared__ int sf, si;
    if (threadIdx.x == 0) { sf = 1; si = 1; }
    __syncthreads();
    if ((threadIdx.x & 31) == 0) {
        if (bf != 0xFFFFFFFFu) atomicAnd(&sf, 0);
        if (bi != 0xFFFFFFFFu) atomicAnd(&si, 0);
    }
    __syncthreads();
    if (threadIdx.x == 0) {
        if (!sf) atomicAnd(&g_fl, 0);
        if (!si) atomicAnd(&g_il, 0);
    }
}

// target==0 focal term (without the (1-ALPHA) factor, folded into the weight)
__device__ __forceinline__ float focneg(float c) {
    c = fminf(fmaxf(c, 1e-4f), 0.9999f);
    return c * c * (-__logf(1.0f - c));
}

// ---------------------------------------------------------------------------
// Kernel 1: main pass. grid = (NB, B), block = 256.
// ---------------------------------------------------------------------------
__global__ void __launch_bounds__(256) k_main(
    const float* __restrict__ cls,     // (B, A, C)
    const float* __restrict__ reg,     // (B, A, 3)
    const float* __restrict__ anc,     // (1, A, 3)
    const float* __restrict__ ann,     // (B, M, 4)
    const void*  __restrict__ states)  // (B, 1, H, W)
{
    const int b    = blockIdx.y;
    const int blk  = blockIdx.x;
    const int tid  = threadIdx.x;
    const int warp = tid >> 5, lane = tid & 31;

    __shared__ float  s_ax[M_N], s_ay[M_N], s_aa[M_N], s_ac[M_N];
    __shared__ float  s_w[8][32];
    __shared__ float4 s_red[256];

    if (tid < M_N) {
        const float* p = ann + (b * M_N + tid) * 4;
        s_ax[tid] = p[0]; s_ay[tid] = p[1]; s_aa[tid] = p[2]; s_ac[tid] = p[3];
    }
    __syncthreads();

    const int a = blk * 256 + tid;
    float acc_c = 0.f, acc_n = 0.f, acc_xy = 0.f, acc_an = 0.f;
    float wv = 0.f;

    if (a < A_N) {
        float ax = anc[a * 3 + 0], ay = anc[a * 3 + 1], aal = anc[a * 3 + 2];

        // nearest annotation by squared xy distance (first-index tie-break)
        float best = 3.4e38f; int bm = 0;
        #pragma unroll 10
        for (int m = 0; m < M_N; m++) {
            float dx = ax - s_ax[m];
            float dy = ay - s_ay[m];
            float d2 = fmaf(dx, dx, dy * dy);
            if (d2 < best) { best = d2; bm = m; }
        }
        float asx = s_ax[bm], asy = s_ay[bm], asa = s_aa[bm], asc = s_ac[bm];
        float dal = fabsf(aal - asa);

        bool pos = (best <= 25.0f)   && (dal <= 10.0f);   // dxy<=5, dal<=10
        bool neg = (best >= 56.25f)  || (dal >= 15.0f);   // dxy>=7.5 or dal>=15

        // gt map lookup: state[b,0,round(ay),round(ax)], half-to-even rounding
        int ix = __float2int_rn(ax);
        int iy = __float2int_rn(ay);
        long sidx = (long)b * (H_N * W_N) + (long)iy * W_N + ix;
        int kind = g_fl ? 1 : (g_il ? 2 : 0);
        bool gt;
        if (kind == 1)      gt = ((const float*)states)[sidx] != 0.0f;
        else if (kind == 2) gt = ((const int*)states)[sidx]   != 0;
        else                gt = ((const unsigned char*)states)[sidx] != 0;
        float damp = gt ? 1.0f : 0.1f;

        // weight for the generic target-0 focal term, (1-ALPHA)=0.05 folded in
        wv = (pos || neg) ? damp * 0.05f : 0.0f;

        if (pos) {
            acc_n = 1.0f;
            // classification correction at the assigned class
            int k = (int)asc;
            float ck = cls[((size_t)b * A_N + a) * C_N + k];
            ck = fminf(fmaxf(ck, 1e-4f), 0.9999f);
            float omc = 1.0f - ck;
            float corr = damp * (0.95f * omc * omc * (-__logf(ck))
                               - 0.05f * ck  * ck  * (-__logf(omc)));
            acc_c += corr;

            // regression losses (only pos anchors contribute)
            const float* r = reg + ((size_t)b * A_N + a) * 3;
            float d0 = fabsf((asx - ax)  - r[0]);
            float d1 = fabsf((asy - ay)  - r[1]);
            float da = fmaxf((fabsf((asa - aal) - r[2]) - 10.0f) * 0.2f, 0.0f);
            float l0 = (d0 <= (1.0f / 9.0f)) ? 4.5f * d0 * d0 : d0 - (1.0f / 18.0f);
            float l1 = (d1 <= (1.0f / 9.0f)) ? 4.5f * d1 * d1 : d1 - (1.0f / 18.0f);
            acc_xy = damp * (l0 + l1);
            acc_an = damp * da;
        }
    }
    s_w[warp][lane] = wv;
    __syncwarp();

    // Phase 2: coalesced stream of this warp's 32 anchors x 80 classes.
    const int wbase = blk * 256 + warp * 32;
    if (wbase < A_N) {
        const float4* p4 = (const float4*)(cls + ((size_t)b * A_N + wbase) * C_N);
        #pragma unroll 4
        for (int j = 0; j < 20; j++) {
            int i4 = j * 32 + lane;               // float4 index within warp block
            float4 v = __ldcs(p4 + i4);           // streaming, evict-first
            float  w = s_w[warp][i4 / 20];        // 20 float4 per anchor
            float  t = focneg(v.x) + focneg(v.y) + focneg(v.z) + focneg(v.w);
            acc_c = fmaf(w, t, acc_c);
        }
    }

    // Phase 3: deterministic block reduction of (cls, npos, xy, ang)
    __syncthreads();
    s_red[tid] = make_float4(acc_c, acc_n, acc_xy, acc_an);
    __syncthreads();
    for (int s = 128; s > 0; s >>= 1) {
        if (tid < s) {
            float4 o = s_red[tid + s];
            float4 m = s_red[tid];
            m.x += o.x; m.y += o.y; m.z += o.z; m.w += o.w;
            s_red[tid] = m;
        }
        __syncthreads();
    }
    if (tid == 0) {
        float4 t = s_red[0];
        float* p = &g_partials[((size_t)b * NB + blk) * 4];
        p[0] = t.x; p[1] = t.y; p[2] = t.z; p[3] = t.w;
    }
}

// ---------------------------------------------------------------------------
// Kernel 2: per-sample reduction (grid = 8, one block per sample), with
// counter-based last-block final combine (deterministic fixed-order sum).
// ---------------------------------------------------------------------------
__global__ void __launch_bounds__(256) k_reduce(float* __restrict__ out) {
    __shared__ float4 s_red[256];
    const int tid = threadIdx.x;
    const int smp = blockIdx.x;

    float4 acc = make_float4(0.f, 0.f, 0.f, 0.f);
    const float4* p4 = (const float4*)&g_partials[(size_t)smp * NB * 4];
    for (int i = tid; i < NB; i += 256) {
        float4 v = p4[i];
        acc.x += v.x; acc.y += v.y; acc.z += v.z; acc.w += v.w;
    }
    s_red[tid] = acc;
    __syncthreads();
    for (int s = 128; s > 0; s >>= 1) {
        if (tid < s) {
            float4 o = s_red[tid + s];
            float4 m = s_red[tid];
            m.x += o.x; m.y += o.y; m.z += o.z; m.w += o.w;
            s_red[tid] = m;
        }
        __syncthreads();
    }

    __shared__ int last;
    if (tid == 0) {
        float4 t  = s_red[0];
        float  np = fmaxf(t.y, 1.0f);
        float  cl = t.x / np;
        float  xl = (t.y > 0.0f) ? t.z / (2.0f * np) : 0.0f;
        float  al = (t.y > 0.0f) ? t.w / np          : 0.0f;
        g_samples[smp * 3 + 0] = cl;
        g_samples[smp * 3 + 1] = xl;
        g_samples[smp * 3 + 2] = al;
        __threadfence();
        int old = atomicAdd(&g_done, 1);
        last = (old == B_N - 1);
    }
    __syncthreads();

    if (last && tid == 0) {
        float cl = 0.f, xl = 0.f, al = 0.f;
        #pragma unroll
        for (int s = 0; s < B_N; s++) {
            cl += g_samples[s * 3 + 0];
            xl += g_samples[s * 3 + 1];
            al += g_samples[s * 3 + 2];
        }
        out[0] = cl * 0.125f;
        out[1] = xl * 0.125f;
        out[2] = al * 0.125f;
    }
}

// ---------------------------------------------------------------------------
extern "C" void kernel_launch(void* const* d_in, const int* in_sizes, int n_in,
                              void* d_out, int out_size) {
    (void)in_sizes; (void)n_in; (void)out_size;
    const float* cls     = (const float*)d_in[0];
    const float* reg     = (const float*)d_in[1];
    const float* anchors = (const float*)d_in[2];
    const float* ann     = (const float*)d_in[3];
    const void*  states  = d_in[4];

    k_init<<<1, 1>>>();
    k_detect<<<256, 256>>>((const uint32_t*)states);
    dim3 grid(NB, B_N);
    k_main<<<grid, 256>>>(cls, reg, anchors, ann, states);
    k_reduce<<<B_N, 256>>>((float*)d_out);
}